// round 10
// baseline (speedup 1.0000x reference)
#include <cuda_runtime.h>
#include <cuda_bf16.h>
#include <cstdint>

// StimulusLayer: dist[b,o] = max_i |x[b,i] - stim[o,i]| (Chebyshev),
// out = state*0.95 + sigmoid((a-dist)*b).  B=128, I=256, O=4096.
//
// R8: fully-unrolled k loop (immediate-offset addressing, deep load hoisting),
// LSU<9% of stream. K1 transposes stim -> stimT[k][o]. K2: block 128thr/4warps,
// tile 8b x 256o (lane <-> o-pair, coalesced LDG.64), x staged once in smem
// (broadcast LDS.128), no barriers in mainloop. 256 blocks = single wave.

#define B_DIM 128
#define I_DIM 256
#define O_DIM 4096

__device__ float g_stimT[I_DIM * O_DIM];      // [k][o], 4 MB

// ---------------- transpose: stim[o][k] -> stimT[k][o] ----------------
__global__ __launch_bounds__(256)
void transpose_kernel(const float* __restrict__ stim)
{
    __shared__ float tile[32][33];
    const int tx = threadIdx.x;               // 0..31
    const int ty = threadIdx.y;               // 0..7
    const int o0 = blockIdx.x * 32;
    const int k0 = blockIdx.y * 32;

    #pragma unroll
    for (int r = 0; r < 4; r++)
        tile[ty + 8 * r][tx] = stim[(o0 + ty + 8 * r) * I_DIM + k0 + tx];
    __syncthreads();
    #pragma unroll
    for (int r = 0; r < 4; r++)
        g_stimT[(k0 + ty + 8 * r) * O_DIM + o0 + tx] = tile[tx][ty + 8 * r];
}

// ---------------- main kernel ----------------
__global__ __launch_bounds__(128, 4)
void stimulus_kernel(const float* __restrict__ x,
                     const float* __restrict__ a,
                     const float* __restrict__ bvec,
                     const float* __restrict__ state,
                     float* __restrict__ out)
{
    __shared__ float xs[8][I_DIM];            // 8 KB, staged once

    const int tid  = threadIdx.x;             // 0..127
    const int w    = tid >> 5;                // warp 0..3
    const int lane = tid & 31;

    const int b0 = blockIdx.y * 8;
    const int o0 = blockIdx.x * 256 + w * 64; // warp's 64-o strip
    const int op = o0 + 2 * lane;             // lane's o-pair

    // ---- stage x tile (8 rows x 64 f4 = 512 f4, 4 per thread) ----
    {
        const float4* __restrict__ x4 = (const float4*)x;
        #pragma unroll
        for (int t = 0; t < 4; t++) {
            int idx = tid + t * 128;          // 0..511
            int row = idx >> 6, col = idx & 63;
            *(float4*)&xs[row][col * 4] = x4[(b0 + row) * (I_DIM / 4) + col];
        }
    }
    __syncthreads();

    const float2* __restrict__ sT = (const float2*)g_stimT + (op >> 1);

    float acc[8][2];
    #pragma unroll
    for (int jb = 0; jb < 8; jb++) { acc[jb][0] = 0.f; acc[jb][1] = 0.f; }

    #pragma unroll
    for (int k8 = 0; k8 < I_DIM / 8; k8++) {  // fully unrolled: imm offsets
        const int k = k8 * 8;

        float2 sv[8];                          // lane's o-pair @ k..k+7
        #pragma unroll
        for (int j = 0; j < 8; j++)
            sv[j] = sT[(k + j) * (O_DIM / 2)]; // coalesced 256B/warp per k

        #pragma unroll
        for (int jb = 0; jb < 8; jb++) {
            const float4 xa = *(const float4*)&xs[jb][k];       // broadcast
            const float4 xb = *(const float4*)&xs[jb][k + 4];   // broadcast
            float m0 = acc[jb][0], m1 = acc[jb][1];
            m0 = fmaxf(m0, fabsf(xa.x - sv[0].x));  m1 = fmaxf(m1, fabsf(xa.x - sv[0].y));
            m0 = fmaxf(m0, fabsf(xa.y - sv[1].x));  m1 = fmaxf(m1, fabsf(xa.y - sv[1].y));
            m0 = fmaxf(m0, fabsf(xa.z - sv[2].x));  m1 = fmaxf(m1, fabsf(xa.z - sv[2].y));
            m0 = fmaxf(m0, fabsf(xa.w - sv[3].x));  m1 = fmaxf(m1, fabsf(xa.w - sv[3].y));
            m0 = fmaxf(m0, fabsf(xb.x - sv[4].x));  m1 = fmaxf(m1, fabsf(xb.x - sv[4].y));
            m0 = fmaxf(m0, fabsf(xb.y - sv[5].x));  m1 = fmaxf(m1, fabsf(xb.y - sv[5].y));
            m0 = fmaxf(m0, fabsf(xb.z - sv[6].x));  m1 = fmaxf(m1, fabsf(xb.z - sv[6].y));
            m0 = fmaxf(m0, fabsf(xb.w - sv[7].x));  m1 = fmaxf(m1, fabsf(xb.w - sv[7].y));
            acc[jb][0] = m0; acc[jb][1] = m1;
        }
    }

    // ---- epilogue ----
    const float2 av = *(const float2*)&a[op];
    const float2 bv = *(const float2*)&bvec[op];
    #pragma unroll
    for (int jb = 0; jb < 8; jb++) {
        const int b = b0 + jb;
        const float2 st = *(const float2*)&state[b * O_DIM + op];
        float2 r;
        r.x = st.x * 0.95f + 1.0f / (1.0f + __expf(-(av.x - acc[jb][0]) * bv.x));
        r.y = st.y * 0.95f + 1.0f / (1.0f + __expf(-(av.y - acc[jb][1]) * bv.y));
        *(float2*)&out[b * O_DIM + op] = r;   // 64 consecutive o per warp
    }
}

extern "C" void kernel_launch(void* const* d_in, const int* in_sizes, int n_in,
                              void* d_out, int out_size)
{
    const float* x     = (const float*)d_in[0];   // (128, 256)
    const float* stim  = (const float*)d_in[1];   // (4096, 256)
    const float* a     = (const float*)d_in[2];   // (4096,)
    const float* bvec  = (const float*)d_in[3];   // (4096,)
    const float* state = (const float*)d_in[4];   // (128, 4096)
    float* out = (float*)d_out;                   // (128, 4096)

    dim3 tgrid(O_DIM / 32, I_DIM / 32);           // 128 x 8
    transpose_kernel<<<tgrid, dim3(32, 8)>>>(stim);

    dim3 grid(O_DIM / 256, B_DIM / 8);            // 16 x 16 = 256 blocks
    stimulus_kernel<<<grid, 128>>>(x, a, bvec, state, out);
}